// round 10
// baseline (speedup 1.0000x reference)
#include <cuda_runtime.h>
#include <cstdint>

// ---------------------------------------------------------------------------
// EncoderSRNN on GB300: 4-CTA cluster per batch element, 512 threads/CTA.
// Full fp32. We/Wh/emb resident in smem; Ws/Wu/Wp streamed from L2 into
// registers with multi-phase prefetch; W_h2i permanently in registers.
// Single-buffer in-place stack, double-buffered hid/tops, 2 cluster syncs.
// ---------------------------------------------------------------------------

#define T_STEPS 127
#define NSEQ    64
#define BSZ     32
#define HDIM    256
#define SDIM    128
#define SSZ     128
#define CSIZE   4
#define NTHR    512

#define OUT_OUTPUTS 0
#define OUT_HID     (T_STEPS*BSZ*HDIM)               // 1040384
#define OUT_STACK   (OUT_HID + BSZ*HDIM)             // 1048576
#define OUT_ACTS    (OUT_STACK + BSZ*SSZ*SDIM)       // 1572864
#define OUT_TOP     (OUT_ACTS + T_STEPS*BSZ*2)       // 1580992

// ---- smem layout (4-byte word offsets) ----
#define W_WE     0        // 16640  f32 [64 o][260]  (k padded 256->260)
#define W_WH     16640    // 16640
#define W_EMB    33280    // 16384  f32 [64 k][256 d]
#define W_STK    49664    // 4096   f32 [128][32] single buffer
#define W_INPP   53760    // 512    f32 [2][256]
#define W_HID    54272    // 512    f32 [2][256]
#define W_TOPS   54784    // 512    f32 [2][256]
#define W_HIDLOC 55296    // 64
#define W_IHLOC  55360    // 64
#define W_COEF   55424    // 128
#define W_BI     55552    // 64
#define W_BH     55616    // 64
#define W_BU     55680    // 32
#define W_BP     55712    // 32
#define W_EMP    55744    // 32
#define W_PUSH   55776    // 32
#define W_UVAL   55808    // 32
#define W_BIAS   55840    // 8
#define W_SCAL   55848    // 8
#define W_PI     55856    // 512  [8][64]  (aliased by pP [4][128])
#define W_PH     56368    // 512  [8][64]
#define W_PU     56880    // 512  [16][32]
#define W_PPART  57392    // 128  [4][32]
#define W_INSTP  57520    // 16
#define SMEM_WORDS 57536
#define SMEM_BYTES (SMEM_WORDS*4)   // 230144

__device__ __forceinline__ uint32_t smem_u32(const void* p) {
    uint32_t a;
    asm("{ .reg .u64 t; cvta.to.shared.u64 t, %1; cvt.u32.u64 %0, t; }" : "=r"(a) : "l"(p));
    return a;
}
__device__ __forceinline__ void st_cluster_f32(uint32_t laddr, uint32_t rank, float v) {
    uint32_t ra;
    asm("mapa.shared::cluster.u32 %0, %1, %2;" : "=r"(ra) : "r"(laddr), "r"(rank));
    asm volatile("st.shared::cluster.f32 [%0], %1;" :: "r"(ra), "f"(v) : "memory");
}
#define CLUSTER_SYNC() do { \
    asm volatile("barrier.cluster.arrive.aligned;" ::: "memory"); \
    asm volatile("barrier.cluster.wait.aligned;"   ::: "memory"); \
} while (0)

__device__ __forceinline__ float dot4(float4 a, float4 b, float acc) {
    return fmaf(a.x, b.x, fmaf(a.y, b.y, fmaf(a.z, b.z, fmaf(a.w, b.w, acc))));
}

__global__ __launch_bounds__(NTHR, 1) __cluster_dims__(CSIZE, 1, 1)
void srnn_kernel(const int* __restrict__ inputs, const float* __restrict__ emb_W,
                 const float* __restrict__ W_e2h, const float* __restrict__ b_e2h,
                 const float* __restrict__ W_s2h, const float* __restrict__ b_s2h,
                 const float* __restrict__ W_h2h, const float* __restrict__ b_h2h,
                 const float* __restrict__ W_h2i, const float* __restrict__ b_h2i,
                 const float* __restrict__ W_h2s, const float* __restrict__ b_h2s,
                 const float* __restrict__ W_s2u, const float* __restrict__ b_s2u,
                 const float* __restrict__ empty_elem, float* __restrict__ out)
{
    extern __shared__ float sm[];
    float* s_we     = sm + W_WE;
    float* s_wh     = sm + W_WH;
    float* s_emb    = sm + W_EMB;
    float* s_stk    = sm + W_STK;
    float* s_inpp   = sm + W_INPP;
    float* s_hid    = sm + W_HID;
    float* s_tops   = sm + W_TOPS;
    float* s_hidloc = sm + W_HIDLOC;
    float* s_ihloc  = sm + W_IHLOC;
    float* s_coef   = sm + W_COEF;
    float* s_bI     = sm + W_BI;
    float* s_bH     = sm + W_BH;
    float* s_bu     = sm + W_BU;
    float* s_bp     = sm + W_BP;
    float* s_emp    = sm + W_EMP;
    float* s_push   = sm + W_PUSH;
    float* s_uval   = sm + W_UVAL;
    float* s_bias   = sm + W_BIAS;
    float* s_scal   = sm + W_SCAL;
    float* s_pI     = sm + W_PI;
    float* s_pH     = sm + W_PH;
    float* s_pU     = sm + W_PU;
    float* s_pP     = sm + W_PI;   // alias: pI dead after C
    float* s_ppart  = sm + W_PPART;
    float* s_instp  = sm + W_INSTP;

    const int tid = threadIdx.x;
    uint32_t r;
    asm("mov.u32 %0, %%cluster_ctarank;" : "=r"(r));
    const int b  = blockIdx.x >> 2;
    const int ri = (int)r;

    const uint32_t a_hid   = smem_u32(s_hid);
    const uint32_t a_tops  = smem_u32(s_tops);
    const uint32_t a_ppart = smem_u32(s_ppart);
    const uint32_t a_instp = smem_u32(s_instp);

    const int wid = tid >> 5, lane = tid & 31;
    const int oB  = tid & 63,  sB = tid >> 6;    // big GEMV: 64 outs x 8 k-slices of 32
    const int oU  = tid & 31,  sU = tid >> 5;    // u: 32 outs x 16 k-slices of 16
    const int oP  = tid & 127, sP = tid >> 7;    // p: 128 outs x 4 k-slices of 16

    // ================= init =================
    for (int idx = tid; idx < 64*256; idx += NTHR) {
        int o = idx >> 8, k = idx & 255;
        s_we[o*260 + k] = W_e2h[(ri*64 + o)*256 + k];
        s_wh[o*260 + k] = W_h2h[(ri*64 + o)*256 + k];
    }
    for (int idx = tid; idx < 64*256; idx += NTHR) {
        int k = idx >> 8, d = idx & 255;
        s_emb[idx] = emb_W[(size_t)inputs[k*BSZ + b]*256 + d];
    }
    for (int idx = tid; idx < 128*32; idx += NTHR)
        s_stk[idx] = empty_elem[ri*32 + (idx & 31)];
    if (tid < 256) { s_hid[tid] = 0.f; s_hid[256+tid] = 0.f;
                     s_tops[tid] = empty_elem[tid & 127]; s_tops[256+tid] = empty_elem[tid & 127]; }
    if (tid < 128) s_coef[tid] = (tid == 0) ? 1.f : 0.f;
    if (tid < 64)  { s_bI[tid] = b_e2h[ri*64 + tid] + b_s2h[ri*64 + tid]; s_bH[tid] = b_h2h[ri*64 + tid]; }
    if (tid < 32)  { s_emp[tid] = empty_elem[ri*32 + tid]; s_bu[tid] = b_s2u[ri*32 + tid]; s_bp[tid] = b_h2s[ri*32 + tid]; }
    if (tid < 3)   s_bias[tid] = b_h2i[tid];

    // W_h2i slice permanently in registers (warps 0-2)
    float whix = 0.f, whiy = 0.f;
    if (wid < 3) {
        whix = W_h2i[wid*256 + ri*64 + 2*lane];
        whiy = W_h2i[wid*256 + ri*64 + 2*lane + 1];
    }

    // Ws prefetch for step 0
    float4 ws[8];
    {
        const float4* g = (const float4*)(W_s2h + (ri*64 + oB)*256 + sB*32);
        #pragma unroll
        for (int q = 0; q < 8; q++) ws[q] = g[q];
    }

    __syncthreads();
    CLUSTER_SYNC();

    for (int t = 0; t < T_STEPS; t++) {
        const int rb = t & 1, wb = rb ^ 1;

        // ---- A: inp partials from smem emb ----
        {
            int d = tid & 255, hf = tid >> 8;
            int kmax = (t < 63) ? t : 63;
            float acc = 0.f;
            for (int k = hf; k <= kmax; k += 2)
                acc = fmaf(s_coef[t - k], s_emb[k*256 + d], acc);
            s_inpp[hf*256 + d] = acc;
        }
        __syncthreads();

        float cc = 0.f, cm = 0.f;
        if (tid < 128) { cc = s_coef[tid]; cm = tid ? s_coef[tid-1] : 0.f; }

        // ---- B: u/p prefetch (consumed in D) + big GEMV (all smem + ws regs) ----
        float4 wu[4], wp[4];
        {
            const float4* gu = (const float4*)(W_s2u + (ri*32 + oU)*256 + sU*16);
            #pragma unroll
            for (int q = 0; q < 4; q++) wu[q] = gu[q];
            const float4* gp = (const float4*)(W_h2s + oP*256 + ri*64 + sP*16);
            #pragma unroll
            for (int q = 0; q < 4; q++) wp[q] = gp[q];
        }
        {
            const float4* we4 = (const float4*)s_we + oB*65;
            const float4* wh4 = (const float4*)s_wh + oB*65;
            const float4* in0 = (const float4*)s_inpp;
            const float4* in1 = in0 + 64;
            const float4* tp4 = (const float4*)(s_tops + rb*256);
            const float4* hd4 = (const float4*)(s_hid  + rb*256);
            float aI = 0.f, aH = 0.f;
            #pragma unroll
            for (int q = 0; q < 8; q++) {
                int kk4 = sB*8 + q;
                float4 x0 = in0[kk4], x1 = in1[kk4];
                float4 xt = tp4[kk4], xh = hd4[kk4];
                float4 we = we4[kk4], wh = wh4[kk4];
                float4 xi = make_float4(x0.x+x1.x, x0.y+x1.y, x0.z+x1.z, x0.w+x1.w);
                aI = dot4(xi, we, aI);
                aI = dot4(xt, ws[q], aI);
                aH = dot4(xh, wh, aH);
            }
            s_pI[tid] = aI;   // tid == sB*64 + oB
            s_pH[tid] = aH;
        }
        __syncthreads();

        // ---- C: reduce big partials; hid DSMEM broadcast ----
        if (tid < 64) {
            float sI = s_bI[tid], sH = s_bH[tid];
            #pragma unroll
            for (int s = 0; s < 8; s++) { sI += s_pI[s*64 + tid]; sH += s_pH[s*64 + tid]; }
            float hn = sI + sH; hn = hn > 0.f ? hn : 0.f;
            s_ihloc[tid]  = sI;
            s_hidloc[tid] = hn;
            out[OUT_OUTPUTS + (t*BSZ + b)*HDIM + ri*64 + tid] = hn;
            if (t == T_STEPS-1) out[OUT_HID + b*HDIM + ri*64 + tid] = hn;
            uint32_t off = a_hid + (uint32_t)(wb*256 + ri*64 + tid)*4u;
            #pragma unroll
            for (uint32_t pr = 0; pr < CSIZE; pr++) st_cluster_f32(off, pr, hn);
        }
        __syncthreads();

        // ---- D: inst partial dots + u partials + p partials (regs + smem) ----
        if (wid < 3) {
            float a = fmaf(s_ihloc[2*lane], whix, s_ihloc[2*lane+1]*whiy);
            #pragma unroll
            for (int off = 16; off; off >>= 1) a += __shfl_down_sync(0xffffffff, a, off);
            if (lane == 0) {
                uint32_t addr = a_instp + (uint32_t)(ri*4 + wid)*4u;
                #pragma unroll
                for (uint32_t pr = 0; pr < CSIZE; pr++) st_cluster_f32(addr, pr, a);
            }
        }
        {
            const float4* tp4 = (const float4*)(s_tops + rb*256);
            float aU = 0.f;
            #pragma unroll
            for (int q = 0; q < 4; q++) aU = dot4(wu[q], tp4[sU*4 + q], aU);
            s_pU[tid] = aU;   // tid == sU*32 + oU

            const float4* hl4 = (const float4*)s_hidloc;
            float aP = 0.f;
            #pragma unroll
            for (int q = 0; q < 4; q++) aP = dot4(wp[q], hl4[sP*4 + q], aP);
            s_pP[tid] = aP;   // tid == sP*128 + oP
        }
        __syncthreads();

        // ---- E: push partial reduce -> DSMEM to owning peer ----
        if (tid < 128) {
            float pv = s_pP[tid] + s_pP[128 + tid] + s_pP[256 + tid] + s_pP[384 + tid];
            st_cluster_f32(a_ppart + (uint32_t)(ri*32 + (tid & 31))*4u, (uint32_t)(tid >> 5), pv);
        }

        CLUSTER_SYNC();   // hid/inst/push partials visible cluster-wide

        // ---- G: Ws prefetch for next step; stack preloads; softmax/push/uval ----
        {
            const float4* g = (const float4*)(W_s2h + (ri*64 + oB)*256 + sB*32);
            #pragma unroll
            for (int q = 0; q < 8; q++) ws[q] = g[q];
        }
        const int j  = tid & 31;
        const int i0 = (tid >> 5)*8;
        float so[10];
        so[0] = (i0 > 0) ? s_stk[(i0-1)*32 + j] : 0.f;
        #pragma unroll
        for (int ii = 0; ii < 9; ii++)
            so[1+ii] = (i0 + ii < 128) ? s_stk[(i0+ii)*32 + j] : 0.f;

        if (tid == 0) {
            float i0v = s_instp[0] + s_instp[4] + s_instp[8]  + s_instp[12] + s_bias[0];
            float i1v = s_instp[1] + s_instp[5] + s_instp[9]  + s_instp[13] + s_bias[1];
            float i2v = s_instp[2] + s_instp[6] + s_instp[10] + s_instp[14] + s_bias[2];
            float m  = fmaxf(i0v, i1v);
            float e0 = expf(i0v - m), e1 = expf(i1v - m);
            float inv = 1.f / (e0 + e1);
            float act0 = e0*inv, act1 = e1*inv;
            float sp = fmaxf(i2v, 0.f) + log1pf(expf(-fabsf(i2v)));
            float g  = 1.f + sp;
            float a0 = powf(act0, g), a1 = powf(act1, g);
            float s  = a0 + a1 + 1e-16f;
            float pp = a0 / s, pq = a1 / s;
            s_scal[0] = pp; s_scal[1] = pq;
            if (r == 0) {
                out[OUT_ACTS + (t*BSZ + b)*2 + 0] = pp;
                out[OUT_ACTS + (t*BSZ + b)*2 + 1] = pq;
            }
        } else if (tid >= 32 && tid < 64) {
            int c = tid - 32;
            float pv = s_ppart[c] + s_ppart[32+c] + s_ppart[64+c] + s_ppart[96+c] + s_bp[c];
            s_push[c] = pv > 0.f ? pv : 0.f;
        } else if (tid >= 64 && tid < 96) {
            int c = tid - 64;
            float u = s_bu[c];
            #pragma unroll
            for (int s = 0; s < 16; s++) u += s_pU[s*32 + c];
            s_uval[c] = u > 0.f ? u : 0.f;
        }
        __syncthreads();

        // ---- I: coef update; in-place stack update; tops bcast ----
        {
            const float pp = s_scal[0], pq = s_scal[1];
            if (tid < 128) s_coef[tid] = fmaf(pp, cc, pq*cm);

            #pragma unroll
            for (int ii = 0; ii < 8; ii++) {
                int i = i0 + ii;
                float nv;
                if (i == 0)        nv = fmaf(pp, s_push[j], pq*s_uval[j]);
                else if (i == 127) nv = fmaf(pp, so[ii],    pq*s_emp[j]);
                else               nv = fmaf(pp, so[ii],    pq*so[ii+2]);
                s_stk[i*32 + j] = nv;
                if (i == 0) out[OUT_TOP + (t*BSZ + b)*SDIM + ri*32 + j] = nv;
                if (i <= 1) {
                    uint32_t off = a_tops + (uint32_t)(wb*256 + i*128 + ri*32 + j)*4u;
                    #pragma unroll
                    for (uint32_t pr = 0; pr < CSIZE; pr++) st_cluster_f32(off, pr, nv);
                }
            }
        }

        CLUSTER_SYNC();   // new tops/coef/stack consistent for next step
    }

    // ---- final stack output ----
    for (int idx = tid; idx < 128*32; idx += NTHR) {
        int i = idx >> 5, j = idx & 31;
        out[OUT_STACK + b*SSZ*SDIM + i*SDIM + ri*32 + j] = s_stk[idx];
    }
}

extern "C" void kernel_launch(void* const* d_in, const int* in_sizes, int n_in,
                              void* d_out, int out_size)
{
    const int*   inputs = (const int*)  d_in[0];
    const float* emb_W  = (const float*)d_in[1];
    const float* W_e2h  = (const float*)d_in[2];
    const float* b_e2h  = (const float*)d_in[3];
    const float* W_s2h  = (const float*)d_in[4];
    const float* b_s2h  = (const float*)d_in[5];
    const float* W_h2h  = (const float*)d_in[6];
    const float* b_h2h  = (const float*)d_in[7];
    const float* W_h2i  = (const float*)d_in[8];
    const float* b_h2i  = (const float*)d_in[9];
    const float* W_h2s  = (const float*)d_in[10];
    const float* b_h2s  = (const float*)d_in[11];
    const float* W_s2u  = (const float*)d_in[12];
    const float* b_s2u  = (const float*)d_in[13];
    const float* empty  = (const float*)d_in[14];
    float* out = (float*)d_out;

    static int configured = 0;
    if (!configured) {
        cudaFuncSetAttribute(srnn_kernel, cudaFuncAttributeMaxDynamicSharedMemorySize, SMEM_BYTES);
        configured = 1;
    }
    srnn_kernel<<<BSZ*CSIZE, NTHR, SMEM_BYTES>>>(inputs, emb_W,
                                                 W_e2h, b_e2h, W_s2h, b_s2h,
                                                 W_h2h, b_h2h, W_h2i, b_h2i,
                                                 W_h2s, b_h2s, W_s2u, b_s2u,
                                                 empty, out);
}

// round 11
// speedup vs baseline: 1.4683x; 1.4683x over previous
#include <cuda_runtime.h>
#include <cstdint>

// ---------------------------------------------------------------------------
// EncoderSRNN on GB300: 4-CTA cluster per batch element, 512 threads/CTA.
// Full fp32. Big-GEMV weights streamed k-major from L2 (prep-transposed,
// coalesced, high MLP). Wu/Wp/emb in smem. inp convolution split into
// gate-independent P/Q sums computed during the softmax slack (phase G),
// finalized in phase I. 4 __syncthreads + 2 cluster syncs per step.
// ---------------------------------------------------------------------------

#define T_STEPS 127
#define NSEQ    64
#define BSZ     32
#define HDIM    256
#define SDIM    128
#define SSZ     128
#define CSIZE   4
#define NTHR    512

#define OUT_OUTPUTS 0
#define OUT_HID     (T_STEPS*BSZ*HDIM)               // 1040384
#define OUT_STACK   (OUT_HID + BSZ*HDIM)             // 1048576
#define OUT_ACTS    (OUT_STACK + BSZ*SSZ*SDIM)       // 1572864
#define OUT_TOP     (OUT_ACTS + T_STEPS*BSZ*2)       // 1580992

// Transposed weights: WT[k][o] = W[o][k]
__device__ __align__(16) float g_WTe[256*256];
__device__ __align__(16) float g_WTs[256*256];
__device__ __align__(16) float g_WTh[256*256];
__device__ __align__(16) float g_WTp[256*128];
__device__ __align__(16) float g_WTu[256*128];

__global__ void prep_kernel(const float* __restrict__ We, const float* __restrict__ Ws,
                            const float* __restrict__ Wh, const float* __restrict__ Wp,
                            const float* __restrict__ Wu) {
    int id = blockIdx.x * blockDim.x + threadIdx.x;   // 262144 total
    if (id < 65536)        { int k = id >> 8,           o = id & 255;  g_WTe[id]          = We[o*256 + k]; }
    else if (id < 131072)  { int r = id - 65536,  k = r >> 8, o = r & 255; g_WTs[r] = Ws[o*256 + k]; }
    else if (id < 196608)  { int r = id - 131072, k = r >> 8, o = r & 255; g_WTh[r] = Wh[o*256 + k]; }
    else if (id < 229376)  { int r = id - 196608, k = r >> 7, o = r & 127; g_WTp[r] = Wp[o*256 + k]; }
    else if (id < 262144)  { int r = id - 229376, k = r >> 7, o = r & 127; g_WTu[r] = Wu[o*256 + k]; }
}

// ---- smem layout (float offsets) ----
#define F_EMB    0        // 16384  [64][256]
#define F_STK    16384    // 8192   [2][128][32]
#define F_WTU    24576    // 8192   [256][32]  owned u-cols
#define F_WTP    32768    // 8192   [64][128]  owned k-rows, all 128 p-cols
#define F_INP    40960    // 256    final inp for current step
#define F_PQ     41216    // 1024   [P0,P1,Q0,Q1][256]
#define F_HID    42240    // 512    [2][256]
#define F_TOPS   42752    // 512    [2][256]
#define F_HIDLOC 43264    // 64
#define F_IHLOC  43328    // 64
#define F_COEF   43392    // 128
#define F_BI     43520    // 64
#define F_BH     43584    // 64
#define F_BU     43648    // 32
#define F_BP     43680    // 32
#define F_EMP    43712    // 32
#define F_PUSH   43744    // 32
#define F_UVAL   43776    // 32
#define F_BIAS   43808    // 4
#define F_SCAL   43812    // 4
#define F_PI     43824    // 2048  [32][64]  (aliased by pP [16][128])
#define F_PH     45872    // 2048  [32][64]
#define F_PU     47920    // 2048  [64][32]
#define F_PPART  49968    // 128   [4][32]
#define F_INSTP  50096    // 16
#define SMEM_FLOATS 50112
#define SMEM_BYTES  (SMEM_FLOATS*4)   // 200448

__device__ __forceinline__ uint32_t smem_u32(const void* p) {
    uint32_t a;
    asm("{ .reg .u64 t; cvta.to.shared.u64 t, %1; cvt.u32.u64 %0, t; }" : "=r"(a) : "l"(p));
    return a;
}
__device__ __forceinline__ void st_cluster_f32(uint32_t laddr, uint32_t rank, float v) {
    uint32_t ra;
    asm("mapa.shared::cluster.u32 %0, %1, %2;" : "=r"(ra) : "r"(laddr), "r"(rank));
    asm volatile("st.shared::cluster.f32 [%0], %1;" :: "r"(ra), "f"(v) : "memory");
}
#define CLUSTER_SYNC() do { \
    asm volatile("barrier.cluster.arrive.aligned;" ::: "memory"); \
    asm volatile("barrier.cluster.wait.aligned;"   ::: "memory"); \
} while (0)

__global__ __launch_bounds__(NTHR, 1) __cluster_dims__(CSIZE, 1, 1)
void srnn_kernel(const int* __restrict__ inputs, const float* __restrict__ emb_W,
                 const float* __restrict__ b_e2h, const float* __restrict__ b_s2h,
                 const float* __restrict__ b_h2h,
                 const float* __restrict__ W_h2i, const float* __restrict__ b_h2i,
                 const float* __restrict__ b_h2s, const float* __restrict__ b_s2u,
                 const float* __restrict__ empty_elem, float* __restrict__ out)
{
    extern __shared__ float sm[];
    float* s_emb   = sm + F_EMB;
    float* s_stk   = sm + F_STK;
    float* s_wtu   = sm + F_WTU;
    float* s_wtp   = sm + F_WTP;
    float* s_inp   = sm + F_INP;
    float* s_pq    = sm + F_PQ;
    float* s_hid   = sm + F_HID;
    float* s_tops  = sm + F_TOPS;
    float* s_hidloc= sm + F_HIDLOC;
    float* s_ihloc = sm + F_IHLOC;
    float* s_coef  = sm + F_COEF;
    float* s_bI    = sm + F_BI;
    float* s_bH    = sm + F_BH;
    float* s_bu    = sm + F_BU;
    float* s_bp    = sm + F_BP;
    float* s_emp   = sm + F_EMP;
    float* s_push  = sm + F_PUSH;
    float* s_uval  = sm + F_UVAL;
    float* s_bias  = sm + F_BIAS;
    float* s_scal  = sm + F_SCAL;
    float* s_pI    = sm + F_PI;
    float* s_pH    = sm + F_PH;
    float* s_pU    = sm + F_PU;
    float* s_pP    = sm + F_PI;   // alias: pI dead after phase C
    float* s_ppart = sm + F_PPART;
    float* s_instp = sm + F_INSTP;

    const int tid = threadIdx.x;
    uint32_t r;
    asm("mov.u32 %0, %%cluster_ctarank;" : "=r"(r));
    const int b  = blockIdx.x >> 2;
    const int ri = (int)r;

    const uint32_t a_hid   = smem_u32(s_hid);
    const uint32_t a_tops  = smem_u32(s_tops);
    const uint32_t a_ppart = smem_u32(s_ppart);
    const uint32_t a_instp = smem_u32(s_instp);

    const int wid = tid >> 5, lane = tid & 31;

    // ================= init =================
    for (int idx = tid; idx < NSEQ*256; idx += NTHR) {
        int row = idx >> 8, d = idx & 255;
        s_emb[idx] = emb_W[(size_t)inputs[row*BSZ + b]*256 + d];
    }
    for (int idx = tid; idx < 128*32; idx += NTHR)
        s_stk[idx] = empty_elem[ri*32 + (idx & 31)];          // stack buf 0
    for (int idx = tid; idx < 256*32; idx += NTHR) {          // owned u-weight cols
        int k = idx >> 5, c = idx & 31;
        s_wtu[idx] = g_WTu[k*128 + ri*32 + c];
    }
    for (int idx = tid; idx < 64*128; idx += NTHR) {          // owned p-weight k-rows
        int kl = idx >> 7, c = idx & 127;
        s_wtp[idx] = g_WTp[(ri*64 + kl)*128 + c];
    }
    if (tid < 256) { s_hid[tid] = 0.f; s_hid[256+tid] = 0.f;
                     s_tops[tid] = empty_elem[tid & 127]; s_tops[256+tid] = empty_elem[tid & 127]; }
    if (tid < 128) s_coef[tid] = (tid == 0) ? 1.f : 0.f;
    if (tid < 64)  { s_bI[tid] = b_e2h[ri*64 + tid] + b_s2h[ri*64 + tid]; s_bH[tid] = b_h2h[ri*64 + tid]; }
    if (tid < 32)  { s_emp[tid] = empty_elem[ri*32 + tid]; s_bu[tid] = b_s2u[ri*32 + tid]; s_bp[tid] = b_h2s[ri*32 + tid]; }
    if (tid < 3)   s_bias[tid] = b_h2i[tid];

    // W_h2i slice permanently in registers (warps 0-2)
    float whix = 0.f, whiy = 0.f;
    if (wid < 3) {
        whix = W_h2i[wid*256 + ri*64 + 2*lane];
        whiy = W_h2i[wid*256 + ri*64 + 2*lane + 1];
    }
    __syncthreads();
    if (tid < 256) s_inp[tid] = s_emb[tid];    // inp(0) = emb row 0
    __syncthreads();
    CLUSTER_SYNC();

    const float4* WTe4 = (const float4*)g_WTe;
    const float4* WTs4 = (const float4*)g_WTs;
    const float4* WTh4 = (const float4*)g_WTh;
    const float4* wtu4 = (const float4*)s_wtu;
    const float4* wtp4 = (const float4*)s_wtp;

    for (int t = 0; t < T_STEPS; t++) {
        const int rb = t & 1, wb = rb ^ 1;

        // ---- B: big GEMV partials (L2 stream) + u partials (smem) ----
        {
            const float* hidr = s_hid  + rb*256;
            const float* topr = s_tops + rb*256;
            const int q = tid & 15, kb = (tid >> 4)*8;
            float4 aI = make_float4(0.f,0.f,0.f,0.f);
            float4 aH = make_float4(0.f,0.f,0.f,0.f);
            #pragma unroll
            for (int kk = 0; kk < 8; kk++) {
                int k = kb + kk;
                float xi = s_inp[k];
                float xt = topr[k], xh = hidr[k];
                float4 we = WTe4[k*64 + ri*16 + q];
                float4 ws = WTs4[k*64 + ri*16 + q];
                float4 wh = WTh4[k*64 + ri*16 + q];
                aI.x = fmaf(xi,we.x,fmaf(xt,ws.x,aI.x));
                aI.y = fmaf(xi,we.y,fmaf(xt,ws.y,aI.y));
                aI.z = fmaf(xi,we.z,fmaf(xt,ws.z,aI.z));
                aI.w = fmaf(xi,we.w,fmaf(xt,ws.w,aI.w));
                aH.x = fmaf(xh,wh.x,aH.x); aH.y = fmaf(xh,wh.y,aH.y);
                aH.z = fmaf(xh,wh.z,aH.z); aH.w = fmaf(xh,wh.w,aH.w);
            }
            ((float4*)s_pI)[(tid>>4)*16 + q] = aI;
            ((float4*)s_pH)[(tid>>4)*16 + q] = aH;

            const int q8 = tid & 7, kbu = (tid >> 3)*4;
            float4 aU = make_float4(0.f,0.f,0.f,0.f);
            #pragma unroll
            for (int kk = 0; kk < 4; kk++) {
                int k = kbu + kk;
                float xt = topr[k];
                float4 wu = wtu4[k*8 + q8];
                aU.x = fmaf(xt,wu.x,aU.x); aU.y = fmaf(xt,wu.y,aU.y);
                aU.z = fmaf(xt,wu.z,aU.z); aU.w = fmaf(xt,wu.w,aU.w);
            }
            ((float4*)s_pU)[(tid>>3)*8 + q8] = aU;
        }
        __syncthreads();

        // ---- C: reduce big partials; hid DSMEM broadcast ----
        if (tid < 64) {
            float sI = s_bI[tid], sH = s_bH[tid];
            #pragma unroll
            for (int s = 0; s < 32; s++) { sI += s_pI[s*64 + tid]; sH += s_pH[s*64 + tid]; }
            float hn = sI + sH; hn = hn > 0.f ? hn : 0.f;
            s_ihloc[tid]  = sI;
            s_hidloc[tid] = hn;
            out[OUT_OUTPUTS + (t*BSZ + b)*HDIM + ri*64 + tid] = hn;
            if (t == T_STEPS-1) out[OUT_HID + b*HDIM + ri*64 + tid] = hn;
            uint32_t off = a_hid + (uint32_t)(wb*256 + ri*64 + tid)*4u;
            #pragma unroll
            for (uint32_t pr = 0; pr < CSIZE; pr++) st_cluster_f32(off, pr, hn);
        }
        __syncthreads();

        // ---- D: inst partial dots (warps 0-2) + push partials (all) ----
        if (wid < 3) {
            float a = fmaf(s_ihloc[2*lane], whix, s_ihloc[2*lane+1]*whiy);
            #pragma unroll
            for (int off = 16; off; off >>= 1) a += __shfl_down_sync(0xffffffff, a, off);
            if (lane == 0) {
                uint32_t addr = a_instp + (uint32_t)(ri*4 + wid)*4u;
                #pragma unroll
                for (uint32_t pr = 0; pr < CSIZE; pr++) st_cluster_f32(addr, pr, a);
            }
        }
        {
            const int q = tid & 31, kb = (tid >> 5)*4;
            float4 aP = make_float4(0.f,0.f,0.f,0.f);
            #pragma unroll
            for (int kk = 0; kk < 4; kk++) {
                int kl = kb + kk;
                float xh = s_hidloc[kl];
                float4 wp = wtp4[kl*32 + q];
                aP.x = fmaf(xh,wp.x,aP.x); aP.y = fmaf(xh,wp.y,aP.y);
                aP.z = fmaf(xh,wp.z,aP.z); aP.w = fmaf(xh,wp.w,aP.w);
            }
            ((float4*)s_pP)[(tid>>5)*32 + q] = aP;
        }
        __syncthreads();

        // ---- E: push partial reduce -> DSMEM to owning peer ----
        if (tid < 128) {
            float pv = 0.f;
            #pragma unroll
            for (int s = 0; s < 16; s++) pv += s_pP[s*128 + tid];
            st_cluster_f32(a_ppart + (uint32_t)(ri*32 + (tid & 31))*4u, (uint32_t)(tid >> 5), pv);
        }

        CLUSTER_SYNC();   // hid/inst/push partials visible cluster-wide

        // ---- G: softmax (warp 0, lane-redundant) + P/Q conv sums (all)
        //         + push finalize (warp 8) + uval (warp 9) ----
        if (wid == 0) {
            float i0v = s_instp[0] + s_instp[4] + s_instp[8]  + s_instp[12] + s_bias[0];
            float i1v = s_instp[1] + s_instp[5] + s_instp[9]  + s_instp[13] + s_bias[1];
            float i2v = s_instp[2] + s_instp[6] + s_instp[10] + s_instp[14] + s_bias[2];
            float m  = fmaxf(i0v, i1v);
            float e0 = expf(i0v - m), e1 = expf(i1v - m);
            float inv = 1.f / (e0 + e1);
            float act0 = e0*inv, act1 = e1*inv;
            float sp = fmaxf(i2v, 0.f) + log1pf(expf(-fabsf(i2v)));
            float g  = 1.f + sp;
            float a0 = powf(act0, g), a1 = powf(act1, g);
            float s  = a0 + a1 + 1e-16f;
            float pp = a0 / s, pq = a1 / s;
            if (lane == 0) {
                s_scal[0] = pp; s_scal[1] = pq;
                if (r == 0) {
                    out[OUT_ACTS + (t*BSZ + b)*2 + 0] = pp;
                    out[OUT_ACTS + (t*BSZ + b)*2 + 1] = pq;
                }
            }
        } else if (wid == 8) {
            int c = tid - 256;
            float pv = s_ppart[c] + s_ppart[32+c] + s_ppart[64+c] + s_ppart[96+c] + s_bp[c];
            s_push[c] = pv > 0.f ? pv : 0.f;
        } else if (wid == 9) {
            int c = tid - 288;
            float u = s_bu[c];
            #pragma unroll
            for (int s = 0; s < 64; s++) u += s_pU[s*32 + c];
            s_uval[c] = u > 0.f ? u : 0.f;
        }
        // P/Q sums for inp(t+1): all threads (2 k-halves per hidden dim).
        // P = sum_k coef[t+1-k]*emb[k], Q = sum_k coef[t-k]*emb[k]
        {
            int d = tid & 255, hf = tid >> 8;
            int kmax = (t + 1 < 63) ? (t + 1) : 63;
            float aP = 0.f, aQ = 0.f;
            for (int k = hf; k <= kmax; k += 2) {
                int j = t + 1 - k;
                float e  = s_emb[k*256 + d];
                float cj = s_coef[j];
                float cm = (j > 0) ? s_coef[j-1] : 0.f;
                aP = fmaf(cj, e, aP);
                aQ = fmaf(cm, e, aQ);
            }
            s_pq[hf*256 + d]       = aP;
            s_pq[512 + hf*256 + d] = aQ;
        }
        float cc = 0.f, cmv = 0.f;
        if (tid < 128) { cc = s_coef[tid]; cmv = tid ? s_coef[tid-1] : 0.f; }
        __syncthreads();

        // ---- I: inp finalize; coef update; stack recurrence; tops bcast ----
        {
            const float pp = s_scal[0], pq = s_scal[1];
            if (tid < 256)
                s_inp[tid] = fmaf(pp, s_pq[tid] + s_pq[256+tid],
                                  pq*(s_pq[512+tid] + s_pq[768+tid]));
            if (tid < 128) s_coef[tid] = fmaf(pp, cc, pq*cmv);

            const float* so = s_stk + rb*4096;
            float*       sn = s_stk + wb*4096;
            const int j = tid & 31, i0 = (tid >> 5)*8;
            float prev = i0 ? so[(i0-1)*32 + j] : 0.f;
            #pragma unroll
            for (int ii = 0; ii < 8; ii++) {
                int i = i0 + ii;
                float nxt = (i == 127) ? 0.f : so[(i+1)*32 + j];
                float nv;
                if (i == 0)        nv = fmaf(pp, s_push[j], pq*s_uval[j]);
                else if (i == 127) nv = fmaf(pp, prev,      pq*s_emp[j]);
                else               nv = fmaf(pp, prev,      pq*nxt);
                sn[i*32 + j] = nv;
                if (i == 0) out[OUT_TOP + (t*BSZ + b)*SDIM + ri*32 + j] = nv;
                if (i <= 1) {
                    uint32_t off = a_tops + (uint32_t)(wb*256 + i*128 + ri*32 + j)*4u;
                    #pragma unroll
                    for (uint32_t pr = 0; pr < CSIZE; pr++) st_cluster_f32(off, pr, nv);
                }
                prev = so[i*32 + j];
            }
        }

        CLUSTER_SYNC();   // new inp/hid/tops/stack consistent for next step
    }

    // ---- final stack output ----
    const float* sf = s_stk + (T_STEPS & 1)*4096;
    for (int idx = tid; idx < 128*32; idx += NTHR) {
        int i = idx >> 5, j = idx & 31;
        out[OUT_STACK + b*SSZ*SDIM + i*SDIM + ri*32 + j] = sf[idx];
    }
}

extern "C" void kernel_launch(void* const* d_in, const int* in_sizes, int n_in,
                              void* d_out, int out_size)
{
    const int*   inputs = (const int*)  d_in[0];
    const float* emb_W  = (const float*)d_in[1];
    const float* W_e2h  = (const float*)d_in[2];
    const float* b_e2h  = (const float*)d_in[3];
    const float* W_s2h  = (const float*)d_in[4];
    const float* b_s2h  = (const float*)d_in[5];
    const float* W_h2h  = (const float*)d_in[6];
    const float* b_h2h  = (const float*)d_in[7];
    const float* W_h2i  = (const float*)d_in[8];
    const float* b_h2i  = (const float*)d_in[9];
    const float* W_h2s  = (const float*)d_in[10];
    const float* b_h2s  = (const float*)d_in[11];
    const float* W_s2u  = (const float*)d_in[12];
    const float* b_s2u  = (const float*)d_in[13];
    const float* empty  = (const float*)d_in[14];
    float* out = (float*)d_out;

    prep_kernel<<<1024, 256>>>(W_e2h, W_s2h, W_h2h, W_h2s, W_s2u);

    static int configured = 0;
    if (!configured) {
        cudaFuncSetAttribute(srnn_kernel, cudaFuncAttributeMaxDynamicSharedMemorySize, SMEM_BYTES);
        configured = 1;
    }
    srnn_kernel<<<BSZ*CSIZE, NTHR, SMEM_BYTES>>>(inputs, emb_W, b_e2h, b_s2h, b_h2h,
                                                 W_h2i, b_h2i, b_h2s, b_s2u, empty, out);
}

// round 13
// speedup vs baseline: 1.8334x; 1.2487x over previous
#include <cuda_runtime.h>
#include <cstdint>

// ---------------------------------------------------------------------------
// EncoderSRNN on GB300: 4-CTA cluster per batch element, 512 threads/CTA.
// Key restructure: We·inp carried directly in output space:
//   E'[k] = We·emb[k] (precomputed, prep2), ihe_{t+1} = pp*Pe + pq*ihe_t,
//   Pe = sum_k coef[t+1-k]*E'[k]  (64 outs/CTA — tiny conv).
// Ws resident in smem; Wh streamed k-major from L2; Wu/Wp in smem.
// Cluster barriers split arrive/wait to overlap local work. Full fp32.
// ---------------------------------------------------------------------------

#define T_STEPS 127
#define BSZ     32
#define HDIM    256
#define SDIM    128
#define SSZ     128
#define CSIZE   4
#define NTHR    512

#define OUT_OUTPUTS 0
#define OUT_HID     (T_STEPS*BSZ*HDIM)               // 1040384
#define OUT_STACK   (OUT_HID + BSZ*HDIM)             // 1048576
#define OUT_ACTS    (OUT_STACK + BSZ*SSZ*SDIM)       // 1572864
#define OUT_TOP     (OUT_ACTS + T_STEPS*BSZ*2)       // 1580992

// Transposed weights: WT[k][o] = W[o][k]
__device__ __align__(16) float g_WTe[256*256];
__device__ __align__(16) float g_WTs[256*256];
__device__ __align__(16) float g_WTh[256*256];
__device__ __align__(16) float g_WTp[256*128];
__device__ __align__(16) float g_WTu[256*128];
// E'_all[b][k][o] = (W_e2h @ emb[b][k])  -- [32][64][256]
__device__ __align__(16) float g_Epr[32*64*256];

__global__ void prep_kernel(const float* __restrict__ We, const float* __restrict__ Ws,
                            const float* __restrict__ Wh, const float* __restrict__ Wp,
                            const float* __restrict__ Wu) {
    int id = blockIdx.x * blockDim.x + threadIdx.x;   // 262144 total
    if (id < 65536)        { int k = id >> 8,           o = id & 255;  g_WTe[id]          = We[o*256 + k]; }
    else if (id < 131072)  { int r = id - 65536,  k = r >> 8, o = r & 255; g_WTs[r] = Ws[o*256 + k]; }
    else if (id < 196608)  { int r = id - 131072, k = r >> 8, o = r & 255; g_WTh[r] = Wh[o*256 + k]; }
    else if (id < 229376)  { int r = id - 196608, k = r >> 7, o = r & 127; g_WTp[r] = Wp[o*256 + k]; }
    else if (id < 262144)  { int r = id - 229376, k = r >> 7, o = r & 127; g_WTu[r] = Wu[o*256 + k]; }
}

// prep2: E'[b][k][o] = sum_d emb[b][k][d] * WTe[d][o].  Block = (b, kb8).
__global__ __launch_bounds__(256) void prep2_kernel(const int* __restrict__ inputs,
                                                    const float* __restrict__ emb_W) {
    __shared__ float s_eT[256*8];   // [d][kk]
    int b  = blockIdx.x >> 3;
    int kb = blockIdx.x & 7;
    int tid = threadIdx.x;
    for (int idx = tid; idx < 8*256; idx += 256) {
        int kk = idx >> 8, d = idx & 255;
        s_eT[d*8 + kk] = emb_W[(size_t)inputs[(kb*8 + kk)*BSZ + b]*256 + d];
    }
    __syncthreads();
    float acc[8] = {0.f,0.f,0.f,0.f,0.f,0.f,0.f,0.f};
    for (int d = 0; d < 256; d++) {
        float w = g_WTe[d*256 + tid];
        float4 e0 = ((const float4*)(s_eT + d*8))[0];
        float4 e1 = ((const float4*)(s_eT + d*8))[1];
        acc[0] = fmaf(w, e0.x, acc[0]); acc[1] = fmaf(w, e0.y, acc[1]);
        acc[2] = fmaf(w, e0.z, acc[2]); acc[3] = fmaf(w, e0.w, acc[3]);
        acc[4] = fmaf(w, e1.x, acc[4]); acc[5] = fmaf(w, e1.y, acc[5]);
        acc[6] = fmaf(w, e1.z, acc[6]); acc[7] = fmaf(w, e1.w, acc[7]);
    }
    #pragma unroll
    for (int kk = 0; kk < 8; kk++)
        g_Epr[((size_t)b*64 + kb*8 + kk)*256 + tid] = acc[kk];
}

// ---- smem layout (float offsets) ----
#define F_WS     0        // 16384  [256 k][64 o] Ws slice
#define F_STK    16384    // 8192   [2][128][32]
#define F_WTU    24576    // 8192   [256][32]
#define F_WTP    32768    // 8192   [64][128]
#define F_EPR    40960    // 4096   E' slice [64 k][64 o]
#define F_HID    45056    // 512    [2][256]
#define F_TOPS   45568    // 512    [2][256]
#define F_HIDLOC 46080    // 64
#define F_IHLOC  46144    // 64
#define F_IHE    46208    // 64
#define F_COEF   46272    // 128
#define F_BI     46400    // 64
#define F_BH     46464    // 64
#define F_BU     46528    // 32
#define F_BP     46560    // 32
#define F_EMP    46592    // 32
#define F_PUSH   46624    // 32
#define F_UVAL   46656    // 32
#define F_BIAS   46688    // 4
#define F_SCAL   46692    // 4
#define F_PS     46720    // 2048  [32][64]  (aliased by pP [16][128])
#define F_PH     48768    // 2048  [32][64]
#define F_PU     50816    // 2048  [64][32]
#define F_PS2    52864    // 512   [8][64]
#define F_PH2    53376    // 512   [8][64]
#define F_PE     53888    // 512   [8][64]
#define F_PU2    54400    // 128   [4][32]
#define F_PPART  54528    // 128   [4][32]
#define F_INSTP  54656    // 16
#define SMEM_FLOATS 54672
#define SMEM_BYTES  (SMEM_FLOATS*4)   // 218688

__device__ __forceinline__ uint32_t smem_u32(const void* p) {
    uint32_t a;
    asm("{ .reg .u64 t; cvta.to.shared.u64 t, %1; cvt.u32.u64 %0, t; }" : "=r"(a) : "l"(p));
    return a;
}
__device__ __forceinline__ void st_cluster_f32(uint32_t laddr, uint32_t rank, float v) {
    uint32_t ra;
    asm("mapa.shared::cluster.u32 %0, %1, %2;" : "=r"(ra) : "r"(laddr), "r"(rank));
    asm volatile("st.shared::cluster.f32 [%0], %1;" :: "r"(ra), "f"(v) : "memory");
}
#define CLUSTER_ARRIVE() asm volatile("barrier.cluster.arrive.aligned;" ::: "memory")
#define CLUSTER_WAIT()   asm volatile("barrier.cluster.wait.aligned;"   ::: "memory")

__global__ __launch_bounds__(NTHR, 1) __cluster_dims__(CSIZE, 1, 1)
void srnn_kernel(const int* __restrict__ inputs, const float* __restrict__ emb_W,
                 const float* __restrict__ b_e2h, const float* __restrict__ b_s2h,
                 const float* __restrict__ b_h2h,
                 const float* __restrict__ W_h2i, const float* __restrict__ b_h2i,
                 const float* __restrict__ b_h2s, const float* __restrict__ b_s2u,
                 const float* __restrict__ empty_elem, float* __restrict__ out)
{
    extern __shared__ float sm[];
    float* s_ws    = sm + F_WS;
    float* s_stk   = sm + F_STK;
    float* s_wtu   = sm + F_WTU;
    float* s_wtp   = sm + F_WTP;
    float* s_epr   = sm + F_EPR;
    float* s_hid   = sm + F_HID;
    float* s_tops  = sm + F_TOPS;
    float* s_hidloc= sm + F_HIDLOC;
    float* s_ihloc = sm + F_IHLOC;
    float* s_ihe   = sm + F_IHE;
    float* s_coef  = sm + F_COEF;
    float* s_bI    = sm + F_BI;
    float* s_bH    = sm + F_BH;
    float* s_bu    = sm + F_BU;
    float* s_bp    = sm + F_BP;
    float* s_emp   = sm + F_EMP;
    float* s_push  = sm + F_PUSH;
    float* s_uval  = sm + F_UVAL;
    float* s_bias  = sm + F_BIAS;
    float* s_scal  = sm + F_SCAL;
    float* s_pS    = sm + F_PS;
    float* s_pH    = sm + F_PH;
    float* s_pU    = sm + F_PU;
    float* s_pS2   = sm + F_PS2;
    float* s_pH2   = sm + F_PH2;
    float* s_pe    = sm + F_PE;
    float* s_pu2   = sm + F_PU2;
    float* s_pP    = sm + F_PS;   // alias: pS dead after C1
    float* s_ppart = sm + F_PPART;
    float* s_instp = sm + F_INSTP;

    const int tid = threadIdx.x;
    uint32_t r;
    asm("mov.u32 %0, %%cluster_ctarank;" : "=r"(r));
    const int b  = blockIdx.x >> 2;
    const int ri = (int)r;

    const uint32_t a_hid   = smem_u32(s_hid);
    const uint32_t a_tops  = smem_u32(s_tops);
    const uint32_t a_ppart = smem_u32(s_ppart);
    const uint32_t a_instp = smem_u32(s_instp);

    const int wid = tid >> 5, lane = tid & 31;

    // ================= init =================
    for (int idx = tid; idx < 256*64; idx += NTHR) {     // Ws slice (smem-resident)
        int k = idx >> 6, o = idx & 63;
        s_ws[idx] = g_WTs[k*256 + ri*64 + o];
    }
    for (int idx = tid; idx < 256*32; idx += NTHR) {     // owned u-weight cols
        int k = idx >> 5, c = idx & 31;
        s_wtu[idx] = g_WTu[k*128 + ri*32 + c];
    }
    for (int idx = tid; idx < 64*128; idx += NTHR) {     // owned p-weight k-rows
        int kl = idx >> 7, c = idx & 127;
        s_wtp[idx] = g_WTp[(ri*64 + kl)*128 + c];
    }
    for (int idx = tid; idx < 64*64; idx += NTHR) {      // E' slice
        int k = idx >> 6, o = idx & 63;
        s_epr[idx] = g_Epr[((size_t)b*64 + k)*256 + ri*64 + o];
    }
    for (int idx = tid; idx < 128*32; idx += NTHR)
        s_stk[idx] = empty_elem[ri*32 + (idx & 31)];     // stack buf 0
    if (tid < 256) { s_hid[tid] = 0.f; s_hid[256+tid] = 0.f;
                     s_tops[tid] = empty_elem[tid & 127]; s_tops[256+tid] = empty_elem[tid & 127]; }
    if (tid < 128) s_coef[tid] = (tid == 0) ? 1.f : 0.f;
    if (tid < 64)  { s_bI[tid] = b_e2h[ri*64 + tid] + b_s2h[ri*64 + tid];
                     s_bH[tid] = b_h2h[ri*64 + tid];
                     s_ihe[tid] = g_Epr[(size_t)b*64*256 + ri*64 + tid]; }  // ihe(0)=E'[0]
    if (tid < 32)  { s_emp[tid] = empty_elem[ri*32 + tid]; s_bu[tid] = b_s2u[ri*32 + tid]; s_bp[tid] = b_h2s[ri*32 + tid]; }
    if (tid < 3)   s_bias[tid] = b_h2i[tid];

    float whix = 0.f, whiy = 0.f;
    if (wid < 3) {
        whix = W_h2i[wid*256 + ri*64 + 2*lane];
        whiy = W_h2i[wid*256 + ri*64 + 2*lane + 1];
    }
    __syncthreads();
    CLUSTER_ARRIVE();     // A0

    const float4* WTh4 = (const float4*)g_WTh;
    const float4* ws4  = (const float4*)s_ws;
    const float4* wtu4 = (const float4*)s_wtu;
    const float4* wtp4 = (const float4*)s_wtp;

    for (int t = 0; t < T_STEPS; t++) {
        const int rb = t & 1, wb = rb ^ 1;

        CLUSTER_WAIT();   // W_top: peers' previous-step tops/hid/stack arrivals

        // ---- B: Ws·tops (smem) + Wh·hid (L2 stream) partials + u partials ----
        {
            const float* hidr = s_hid  + rb*256;
            const float* topr = s_tops + rb*256;
            const int q = tid & 15, kb = (tid >> 4)*8;
            float4 aS = make_float4(0.f,0.f,0.f,0.f);
            float4 aH = make_float4(0.f,0.f,0.f,0.f);
            #pragma unroll
            for (int kk = 0; kk < 8; kk++) {
                int k = kb + kk;
                float xt = topr[k], xh = hidr[k];
                float4 ws = ws4[k*16 + q];
                float4 wh = WTh4[k*64 + ri*16 + q];
                aS.x = fmaf(xt,ws.x,aS.x); aS.y = fmaf(xt,ws.y,aS.y);
                aS.z = fmaf(xt,ws.z,aS.z); aS.w = fmaf(xt,ws.w,aS.w);
                aH.x = fmaf(xh,wh.x,aH.x); aH.y = fmaf(xh,wh.y,aH.y);
                aH.z = fmaf(xh,wh.z,aH.z); aH.w = fmaf(xh,wh.w,aH.w);
            }
            ((float4*)s_pS)[(tid>>4)*16 + q] = aS;
            ((float4*)s_pH)[(tid>>4)*16 + q] = aH;

            const int q8 = tid & 7, kbu = (tid >> 3)*4;
            float4 aU = make_float4(0.f,0.f,0.f,0.f);
            #pragma unroll
            for (int kk = 0; kk < 4; kk++) {
                int k = kbu + kk;
                float xt = topr[k];
                float4 wu = wtu4[k*8 + q8];
                aU.x = fmaf(xt,wu.x,aU.x); aU.y = fmaf(xt,wu.y,aU.y);
                aU.z = fmaf(xt,wu.z,aU.z); aU.w = fmaf(xt,wu.w,aU.w);
            }
            ((float4*)s_pU)[(tid>>3)*8 + q8] = aU;
        }
        __syncthreads();   // s1

        // ---- C1: tree-reduce stage (32 -> 8 slices) ----
        {
            const int o = tid & 63, g = tid >> 6;
            float sS = s_pS[(4*g+0)*64+o] + s_pS[(4*g+1)*64+o]
                     + s_pS[(4*g+2)*64+o] + s_pS[(4*g+3)*64+o];
            float sH = s_pH[(4*g+0)*64+o] + s_pH[(4*g+1)*64+o]
                     + s_pH[(4*g+2)*64+o] + s_pH[(4*g+3)*64+o];
            s_pS2[g*64 + o] = sS;
            s_pH2[g*64 + o] = sH;
        }
        __syncthreads();   // s2

        // ---- C2: finalize hid/ihid; DSMEM hid broadcast ----
        if (tid < 64) {
            float sI = s_ihe[tid] + s_bI[tid];
            float sH = s_bH[tid];
            #pragma unroll
            for (int s = 0; s < 8; s++) { sI += s_pS2[s*64 + tid]; sH += s_pH2[s*64 + tid]; }
            float hn = sI + sH; hn = hn > 0.f ? hn : 0.f;
            s_ihloc[tid]  = sI;
            s_hidloc[tid] = hn;
            out[OUT_OUTPUTS + (t*BSZ + b)*HDIM + ri*64 + tid] = hn;
            if (t == T_STEPS-1) out[OUT_HID + b*HDIM + ri*64 + tid] = hn;
            uint32_t off = a_hid + (uint32_t)(wb*256 + ri*64 + tid)*4u;
            #pragma unroll
            for (uint32_t pr = 0; pr < CSIZE; pr++) st_cluster_f32(off, pr, hn);
        }
        __syncthreads();   // s3

        // ---- D: inst partial dots (warps 0-2) + push partials (all) ----
        if (wid < 3) {
            float a = fmaf(s_ihloc[2*lane], whix, s_ihloc[2*lane+1]*whiy);
            #pragma unroll
            for (int off = 16; off; off >>= 1) a += __shfl_down_sync(0xffffffff, a, off);
            if (lane == 0) {
                uint32_t addr = a_instp + (uint32_t)(ri*4 + wid)*4u;
                #pragma unroll
                for (uint32_t pr = 0; pr < CSIZE; pr++) st_cluster_f32(addr, pr, a);
            }
        }
        {
            const int q = tid & 31, kb = (tid >> 5)*4;
            float4 aP = make_float4(0.f,0.f,0.f,0.f);
            #pragma unroll
            for (int kk = 0; kk < 4; kk++) {
                int kl = kb + kk;
                float xh = s_hidloc[kl];
                float4 wp = wtp4[kl*32 + q];
                aP.x = fmaf(xh,wp.x,aP.x); aP.y = fmaf(xh,wp.y,aP.y);
                aP.z = fmaf(xh,wp.z,aP.z); aP.w = fmaf(xh,wp.w,aP.w);
            }
            ((float4*)s_pP)[(tid>>5)*32 + q] = aP;
        }
        __syncthreads();   // s4

        // ---- E: push reduce -> DSMEM; u tree stage (pre-arrive for ordering) ----
        if (tid < 128) {
            float pv = 0.f;
            #pragma unroll
            for (int s = 0; s < 16; s++) pv += s_pP[s*128 + tid];
            st_cluster_f32(a_ppart + (uint32_t)(ri*32 + (tid & 31))*4u, (uint32_t)(tid >> 5), pv);
        } else if (tid < 256) {
            int c = (tid - 128) & 31, g4 = (tid - 128) >> 5;
            float u = 0.f;
            #pragma unroll
            for (int s = 0; s < 16; s++) u += s_pU[(16*g4 + s)*32 + c];
            s_pu2[g4*32 + c] = u;
        }

        CLUSTER_ARRIVE();  // A_mid (hid/instp/ppart/pu2 stores all precede)

        // ---- G-local: Pe conv over E' + stack/coef preloads (peer-independent) ----
        float cc = 0.f, cm = 0.f;
        float so[10];
        const int j  = tid & 31;
        const int i0 = (tid >> 5)*8;
        {
            const int o = tid & 63, ks = tid >> 6;
            const int kmax = (t + 1 < 63) ? (t + 1) : 63;
            float acc = 0.f;
            const int kend = (ks*8 + 8 <= kmax + 1) ? ks*8 + 8 : kmax + 1;
            for (int k = ks*8; k < kend; k++)
                acc = fmaf(s_coef[t + 1 - k], s_epr[k*64 + o], acc);
            s_pe[ks*64 + o] = acc;

            if (tid < 128) { cc = s_coef[tid]; cm = tid ? s_coef[tid-1] : 0.f; }
            const float* stkr = s_stk + rb*4096;
            so[0] = (i0 > 0) ? stkr[(i0-1)*32 + j] : 0.f;
            #pragma unroll
            for (int ii = 0; ii < 9; ii++)
                so[1+ii] = (i0 + ii < 128) ? stkr[(i0+ii)*32 + j] : 0.f;
        }

        CLUSTER_WAIT();    // W_mid

        // ---- G2: softmax (warp 0) + push finalize (warp 8) + uval (warp 9) ----
        if (wid == 0) {
            float i0v = s_instp[0] + s_instp[4] + s_instp[8]  + s_instp[12] + s_bias[0];
            float i1v = s_instp[1] + s_instp[5] + s_instp[9]  + s_instp[13] + s_bias[1];
            float i2v = s_instp[2] + s_instp[6] + s_instp[10] + s_instp[14] + s_bias[2];
            float m  = fmaxf(i0v, i1v);
            float e0 = expf(i0v - m), e1 = expf(i1v - m);
            float inv = 1.f / (e0 + e1);
            float act0 = e0*inv, act1 = e1*inv;
            float sp = fmaxf(i2v, 0.f) + log1pf(expf(-fabsf(i2v)));
            float g  = 1.f + sp;
            float a0 = powf(act0, g), a1 = powf(act1, g);
            float s  = a0 + a1 + 1e-16f;
            float pp = a0 / s, pq = a1 / s;
            if (lane == 0) {
                s_scal[0] = pp; s_scal[1] = pq;
                if (r == 0) {
                    out[OUT_ACTS + (t*BSZ + b)*2 + 0] = pp;
                    out[OUT_ACTS + (t*BSZ + b)*2 + 1] = pq;
                }
            }
        } else if (wid == 8) {
            int c = tid - 256;
            float pv = s_ppart[c] + s_ppart[32+c] + s_ppart[64+c] + s_ppart[96+c] + s_bp[c];
            s_push[c] = pv > 0.f ? pv : 0.f;
        } else if (wid == 9) {
            int c = tid - 288;
            float u = s_pu2[c] + s_pu2[32+c] + s_pu2[64+c] + s_pu2[96+c] + s_bu[c];
            s_uval[c] = u > 0.f ? u : 0.f;
        }
        __syncthreads();   // s5

        // ---- I1: ihe/coef update + stack rows 0,1 + tops DSMEM ----
        const float pp = s_scal[0], pq = s_scal[1];
        float* stkw = s_stk + wb*4096;
        if (tid < 64) {
            float Pe = 0.f;
            #pragma unroll
            for (int s = 0; s < 8; s++) Pe += s_pe[s*64 + tid];
            s_ihe[tid] = fmaf(pp, Pe, pq*s_ihe[tid]);
        }
        if (tid < 128) s_coef[tid] = fmaf(pp, cc, pq*cm);
        {
            #pragma unroll
            for (int ii = 0; ii < 2; ii++) {
                int i = i0 + ii;
                float nv;
                if (i == 0)        nv = fmaf(pp, s_push[j], pq*s_uval[j]);
                else               nv = fmaf(pp, so[ii],    pq*so[ii+2]);
                stkw[i*32 + j] = nv;
                if (i == 0) out[OUT_TOP + (t*BSZ + b)*SDIM + ri*32 + j] = nv;
                if (i <= 1) {
                    uint32_t off = a_tops + (uint32_t)(wb*256 + i*128 + ri*32 + j)*4u;
                    #pragma unroll
                    for (uint32_t pr = 0; pr < CSIZE; pr++) st_cluster_f32(off, pr, nv);
                }
            }
        }

        CLUSTER_ARRIVE();  // A_end (tops/hid/stack rows 0,1 done)

        // ---- I2: stack rows 2..7 (local only; ordered by s1 of next step) ----
        {
            #pragma unroll
            for (int ii = 2; ii < 8; ii++) {
                int i = i0 + ii;
                float nv;
                if (i == 127) nv = fmaf(pp, so[ii], pq*s_emp[j]);
                else          nv = fmaf(pp, so[ii], pq*so[ii+2]);
                stkw[i*32 + j] = nv;
            }
        }
    }

    CLUSTER_WAIT();        // match final arrive before exit

    // ---- final stack output ----
    const float* sf = s_stk + (T_STEPS & 1)*4096;
    for (int idx = tid; idx < 128*32; idx += NTHR) {
        int i = idx >> 5, jc = idx & 31;
        out[OUT_STACK + b*SSZ*SDIM + i*SDIM + ri*32 + jc] = sf[idx];
    }
}

extern "C" void kernel_launch(void* const* d_in, const int* in_sizes, int n_in,
                              void* d_out, int out_size)
{
    const int*   inputs = (const int*)  d_in[0];
    const float* emb_W  = (const float*)d_in[1];
    const float* W_e2h  = (const float*)d_in[2];
    const float* b_e2h  = (const float*)d_in[3];
    const float* W_s2h  = (const float*)d_in[4];
    const float* b_s2h  = (const float*)d_in[5];
    const float* W_h2h  = (const float*)d_in[6];
    const float* b_h2h  = (const float*)d_in[7];
    const float* W_h2i  = (const float*)d_in[8];
    const float* b_h2i  = (const float*)d_in[9];
    const float* W_h2s  = (const float*)d_in[10];
    const float* b_h2s  = (const float*)d_in[11];
    const float* W_s2u  = (const float*)d_in[12];
    const float* b_s2u  = (const float*)d_in[13];
    const float* empty  = (const float*)d_in[14];
    float* out = (float*)d_out;

    prep_kernel<<<1024, 256>>>(W_e2h, W_s2h, W_h2h, W_h2s, W_s2u);
    prep2_kernel<<<256, 256>>>(inputs, emb_W);

    static int configured = 0;
    if (!configured) {
        cudaFuncSetAttribute(srnn_kernel, cudaFuncAttributeMaxDynamicSharedMemorySize, SMEM_BYTES);
        configured = 1;
    }
    srnn_kernel<<<BSZ*CSIZE, NTHR, SMEM_BYTES>>>(inputs, emb_W, b_e2h, b_s2h, b_h2h,
                                                 W_h2i, b_h2i, b_h2s, b_s2u, empty, out);
}

// round 14
// speedup vs baseline: 2.2957x; 1.2521x over previous
#include <cuda_runtime.h>
#include <cstdint>

// ---------------------------------------------------------------------------
// EncoderSRNN on GB300: 4-CTA cluster per batch element, 512 threads/CTA.
// All weights (Ws, Wh, Wu, Wp) smem-resident; E' (We@emb) precomputed and
// streamed from L2 in an overlapped phase. mbarrier point-to-point cluster
// sync (no barrier.cluster in the loop); only 2 of 16 warps block on the
// mid-step exchange. Single-buffer stack with register staging. Full fp32.
// ---------------------------------------------------------------------------

#define T_STEPS 127
#define BSZ     32
#define HDIM    256
#define SDIM    128
#define SSZ     128
#define CSIZE   4
#define NTHR    512

#define OUT_OUTPUTS 0
#define OUT_HID     (T_STEPS*BSZ*HDIM)               // 1040384
#define OUT_STACK   (OUT_HID + BSZ*HDIM)             // 1048576
#define OUT_ACTS    (OUT_STACK + BSZ*SSZ*SDIM)       // 1572864
#define OUT_TOP     (OUT_ACTS + T_STEPS*BSZ*2)       // 1580992

// Transposed weights: WT[k][o] = W[o][k]
__device__ __align__(16) float g_WTe[256*256];
__device__ __align__(16) float g_WTs[256*256];
__device__ __align__(16) float g_WTh[256*256];
__device__ __align__(16) float g_WTp[256*128];
__device__ __align__(16) float g_WTu[256*128];
// E'_all[b][k][o] = (W_e2h @ emb[b][k])  -- [32][64][256]
__device__ __align__(16) float g_Epr[32*64*256];

__global__ void prep_kernel(const float* __restrict__ We, const float* __restrict__ Ws,
                            const float* __restrict__ Wh, const float* __restrict__ Wp,
                            const float* __restrict__ Wu) {
    int id = blockIdx.x * blockDim.x + threadIdx.x;   // 262144 total
    if (id < 65536)        { int k = id >> 8,           o = id & 255;  g_WTe[id]          = We[o*256 + k]; }
    else if (id < 131072)  { int r = id - 65536,  k = r >> 8, o = r & 255; g_WTs[r] = Ws[o*256 + k]; }
    else if (id < 196608)  { int r = id - 131072, k = r >> 8, o = r & 255; g_WTh[r] = Wh[o*256 + k]; }
    else if (id < 229376)  { int r = id - 196608, k = r >> 7, o = r & 127; g_WTp[r] = Wp[o*256 + k]; }
    else if (id < 262144)  { int r = id - 229376, k = r >> 7, o = r & 127; g_WTu[r] = Wu[o*256 + k]; }
}

// prep2: E'[b][k][o] = sum_d emb[b][k][d] * WTe[d][o].  Block = (b, kb8).
__global__ __launch_bounds__(256) void prep2_kernel(const int* __restrict__ inputs,
                                                    const float* __restrict__ emb_W) {
    __shared__ float s_eT[256*8];   // [d][kk]
    int b  = blockIdx.x >> 3;
    int kb = blockIdx.x & 7;
    int tid = threadIdx.x;
    for (int idx = tid; idx < 8*256; idx += 256) {
        int kk = idx >> 8, d = idx & 255;
        s_eT[d*8 + kk] = emb_W[(size_t)inputs[(kb*8 + kk)*BSZ + b]*256 + d];
    }
    __syncthreads();
    float acc[8] = {0.f,0.f,0.f,0.f,0.f,0.f,0.f,0.f};
    for (int d = 0; d < 256; d++) {
        float w = g_WTe[d*256 + tid];
        float4 e0 = ((const float4*)(s_eT + d*8))[0];
        float4 e1 = ((const float4*)(s_eT + d*8))[1];
        acc[0] = fmaf(w, e0.x, acc[0]); acc[1] = fmaf(w, e0.y, acc[1]);
        acc[2] = fmaf(w, e0.z, acc[2]); acc[3] = fmaf(w, e0.w, acc[3]);
        acc[4] = fmaf(w, e1.x, acc[4]); acc[5] = fmaf(w, e1.y, acc[5]);
        acc[6] = fmaf(w, e1.z, acc[6]); acc[7] = fmaf(w, e1.w, acc[7]);
    }
    #pragma unroll
    for (int kk = 0; kk < 8; kk++)
        g_Epr[((size_t)b*64 + kb*8 + kk)*256 + tid] = acc[kk];
}

// ---- smem layout (float offsets) ----
#define F_WS     0        // [256 k][64 o]   16384
#define F_WH     16384    // [256 k][64 o]   16384
#define F_WU     32768    // [256 k][32 o]   8192
#define F_WP     40960    // [64 kl][128 o]  8192
#define F_STK    49152    // [128][32]       4096  (single buffer)
#define F_HID    53248    // [2][256]        512
#define F_TOPS   53760    // [2][256]        512
#define F_PS     54272    // [16][64]        1024  (pP [16][128] aliases PS+PH)
#define F_PH     55296    // [16][64]        1024
#define F_PU     56320    // [16][32]        512   (pe [8][64] aliases)
#define F_HIDLOC 56832    // 64
#define F_IHE    56896    // 64
#define F_COEF   56960    // 128
#define F_BI     57088    // 64
#define F_BH     57152    // 64
#define F_BU     57216    // 32
#define F_BP     57248    // 32
#define F_EMP    57280    // 32
#define F_PUSH   57312    // 32
#define F_UVAL   57344    // 32
#define F_BIAS   57376    // 4
#define F_SCAL   57380    // 4
#define F_INSTW  57384    // 8  ([2 warps][3] partial logits)
#define F_PPART  57392    // 128  [4 src][32]
#define F_INSTP  57520    // 16   [4 src][4]
#define F_MBAR   57536    // 4 floats: mid @ +0B, end @ +8B (8B aligned)
#define SMEM_FLOATS 57540
#define SMEM_BYTES  (SMEM_FLOATS*4)   // 230160

__device__ __forceinline__ uint32_t smem_u32(const void* p) {
    uint32_t a;
    asm("{ .reg .u64 t; cvta.to.shared.u64 t, %1; cvt.u32.u64 %0, t; }" : "=r"(a) : "l"(p));
    return a;
}
__device__ __forceinline__ void st_cluster_f32(uint32_t laddr, uint32_t rank, float v) {
    uint32_t ra;
    asm("mapa.shared::cluster.u32 %0, %1, %2;" : "=r"(ra) : "r"(laddr), "r"(rank));
    asm volatile("st.shared::cluster.f32 [%0], %1;" :: "r"(ra), "f"(v) : "memory");
}
// Arrive on the mbarrier at the same smem offset in cluster CTA `rank`.
__device__ __forceinline__ void mbar_arrive_cluster(uint32_t laddr, uint32_t rank) {
    asm volatile(
        "{\n\t"
        ".reg .b32 ra;\n\t"
        "mapa.shared::cluster.u32 ra, %0, %1;\n\t"
        "mbarrier.arrive.shared::cluster.b64 _, [ra];\n\t"
        "}"
        :: "r"(laddr), "r"(rank) : "memory");
}
// Cluster-scope acquire wait on local mbarrier phase parity.
__device__ __forceinline__ void mbar_wait_cluster(uint32_t mbar, uint32_t parity) {
    asm volatile(
        "{\n\t"
        ".reg .pred P;\n\t"
        "WAIT_%=:\n\t"
        "mbarrier.try_wait.parity.acquire.cluster.shared::cta.b64 P, [%0], %1, 0x989680;\n\t"
        "@P bra.uni DONE_%=;\n\t"
        "bra.uni WAIT_%=;\n\t"
        "DONE_%=:\n\t"
        "}"
        :: "r"(mbar), "r"(parity) : "memory");
}
#define CLUSTER_SYNC() do { \
    asm volatile("barrier.cluster.arrive.aligned;" ::: "memory"); \
    asm volatile("barrier.cluster.wait.aligned;"   ::: "memory"); \
} while (0)

__global__ __launch_bounds__(NTHR, 1) __cluster_dims__(CSIZE, 1, 1)
void srnn_kernel(const float* __restrict__ b_e2h, const float* __restrict__ b_s2h,
                 const float* __restrict__ b_h2h,
                 const float* __restrict__ W_h2i, const float* __restrict__ b_h2i,
                 const float* __restrict__ b_h2s, const float* __restrict__ b_s2u,
                 const float* __restrict__ empty_elem, float* __restrict__ out)
{
    extern __shared__ float sm[];
    float* s_ws    = sm + F_WS;
    float* s_wh    = sm + F_WH;
    float* s_wu    = sm + F_WU;
    float* s_wp    = sm + F_WP;
    float* s_stk   = sm + F_STK;
    float* s_hid   = sm + F_HID;
    float* s_tops  = sm + F_TOPS;
    float* s_pS    = sm + F_PS;
    float* s_pH    = sm + F_PH;
    float* s_pU    = sm + F_PU;
    float* s_pe    = sm + F_PU;    // alias: pU dead after E, pe lives G..I1
    float* s_pP    = sm + F_PS;    // alias: pS/pH dead after C2
    float* s_hidloc= sm + F_HIDLOC;
    float* s_ihe   = sm + F_IHE;
    float* s_coef  = sm + F_COEF;
    float* s_bI    = sm + F_BI;
    float* s_bH    = sm + F_BH;
    float* s_bu    = sm + F_BU;
    float* s_bp    = sm + F_BP;
    float* s_emp   = sm + F_EMP;
    float* s_push  = sm + F_PUSH;
    float* s_uval  = sm + F_UVAL;
    float* s_bias  = sm + F_BIAS;
    float* s_scal  = sm + F_SCAL;
    float* s_instw = sm + F_INSTW;
    float* s_ppart = sm + F_PPART;
    float* s_instp = sm + F_INSTP;

    const int tid = threadIdx.x;
    uint32_t r;
    asm("mov.u32 %0, %%cluster_ctarank;" : "=r"(r));
    const int b  = blockIdx.x >> 2;
    const int ri = (int)r;

    const uint32_t a_hid   = smem_u32(s_hid);
    const uint32_t a_tops  = smem_u32(s_tops);
    const uint32_t a_ppart = smem_u32(s_ppart);
    const uint32_t a_instp = smem_u32(s_instp);
    const uint32_t a_mid   = smem_u32(sm + F_MBAR);
    const uint32_t a_end   = a_mid + 8;

    const int wid = tid >> 5, lane = tid & 31;

    // ================= init =================
    for (int idx = tid; idx < 256*64; idx += NTHR) {     // Ws, Wh slices
        int k = idx >> 6, o = idx & 63;
        s_ws[idx] = g_WTs[k*256 + ri*64 + o];
        s_wh[idx] = g_WTh[k*256 + ri*64 + o];
    }
    for (int idx = tid; idx < 256*32; idx += NTHR) {     // Wu slice (owned 32 outs)
        int k = idx >> 5, c = idx & 31;
        s_wu[idx] = g_WTu[k*128 + ri*32 + c];
    }
    for (int idx = tid; idx < 64*128; idx += NTHR) {     // Wp slice (owned 64 k-rows)
        int kl = idx >> 7, c = idx & 127;
        s_wp[idx] = g_WTp[(ri*64 + kl)*128 + c];
    }
    for (int idx = tid; idx < 128*32; idx += NTHR)
        s_stk[idx] = empty_elem[ri*32 + (idx & 31)];
    if (tid < 256) { s_hid[tid] = 0.f; s_hid[256+tid] = 0.f;
                     s_tops[tid] = empty_elem[tid & 127]; s_tops[256+tid] = empty_elem[tid & 127]; }
    if (tid < 128) s_coef[tid] = (tid == 0) ? 1.f : 0.f;
    if (tid < 64)  { s_bI[tid] = b_e2h[ri*64 + tid] + b_s2h[ri*64 + tid];
                     s_bH[tid] = b_h2h[ri*64 + tid];
                     s_ihe[tid] = g_Epr[(size_t)b*64*256 + ri*64 + tid]; }
    if (tid < 32)  { s_emp[tid] = empty_elem[ri*32 + tid]; s_bu[tid] = b_s2u[ri*32 + tid]; s_bp[tid] = b_h2s[ri*32 + tid]; }
    if (tid < 3)   s_bias[tid] = b_h2i[tid];
    if (tid == 0) {
        asm volatile("mbarrier.init.shared.b64 [%0], %1;" :: "r"(a_mid), "r"((uint32_t)CSIZE) : "memory");
        asm volatile("mbarrier.init.shared.b64 [%0], %1;" :: "r"(a_end), "r"((uint32_t)CSIZE) : "memory");
    }

    // W_h2i columns for owned 64 ihid dims (tid<64)
    float whi0 = 0.f, whi1 = 0.f, whi2 = 0.f;
    if (tid < 64) {
        whi0 = W_h2i[0*256 + ri*64 + tid];
        whi1 = W_h2i[1*256 + ri*64 + tid];
        whi2 = W_h2i[2*256 + ri*64 + tid];
    }
    __syncthreads();
    CLUSTER_SYNC();                    // mbar init visible cluster-wide
    if (tid < CSIZE) mbar_arrive_cluster(a_end, (uint32_t)tid);   // end phase 0

    const float4* ws4  = (const float4*)s_ws;
    const float4* wh4  = (const float4*)s_wh;
    const float4* wu4  = (const float4*)s_wu;
    const float4* wp4  = (const float4*)s_wp;

    for (int t = 0; t < T_STEPS; t++) {
        const int rb = t & 1, wb = rb ^ 1;

        mbar_wait_cluster(a_end, (uint32_t)(t & 1));   // peers' prior-step data

        // ---- B: big GEMV (Ws,Wh smem) + u partials; in-warp shfl reduce ----
        {
            const float* hidr = s_hid  + rb*256;
            const float* topr = s_tops + rb*256;
            const int q = tid & 15, kb = (tid >> 4)*8;
            float4 aS = make_float4(0.f,0.f,0.f,0.f);
            float4 aH = make_float4(0.f,0.f,0.f,0.f);
            #pragma unroll
            for (int kk = 0; kk < 8; kk++) {
                int k = kb + kk;
                float xt = topr[k], xh = hidr[k];
                float4 ws = ws4[k*16 + q];
                float4 wh = wh4[k*16 + q];
                aS.x = fmaf(xt,ws.x,aS.x); aS.y = fmaf(xt,ws.y,aS.y);
                aS.z = fmaf(xt,ws.z,aS.z); aS.w = fmaf(xt,ws.w,aS.w);
                aH.x = fmaf(xh,wh.x,aH.x); aH.y = fmaf(xh,wh.y,aH.y);
                aH.z = fmaf(xh,wh.z,aH.z); aH.w = fmaf(xh,wh.w,aH.w);
            }
            aS.x += __shfl_xor_sync(0xffffffffu, aS.x, 16);
            aS.y += __shfl_xor_sync(0xffffffffu, aS.y, 16);
            aS.z += __shfl_xor_sync(0xffffffffu, aS.z, 16);
            aS.w += __shfl_xor_sync(0xffffffffu, aS.w, 16);
            aH.x += __shfl_xor_sync(0xffffffffu, aH.x, 16);
            aH.y += __shfl_xor_sync(0xffffffffu, aH.y, 16);
            aH.z += __shfl_xor_sync(0xffffffffu, aH.z, 16);
            aH.w += __shfl_xor_sync(0xffffffffu, aH.w, 16);
            if (lane < 16) {
                ((float4*)s_pS)[wid*16 + q] = aS;
                ((float4*)s_pH)[wid*16 + q] = aH;
            }

            const int q8 = tid & 7, ku = (tid >> 3)*4;
            float4 aU = make_float4(0.f,0.f,0.f,0.f);
            #pragma unroll
            for (int kk = 0; kk < 4; kk++) {
                int k = ku + kk;
                float xt = topr[k];
                float4 wu = wu4[k*8 + q8];
                aU.x = fmaf(xt,wu.x,aU.x); aU.y = fmaf(xt,wu.y,aU.y);
                aU.z = fmaf(xt,wu.z,aU.z); aU.w = fmaf(xt,wu.w,aU.w);
            }
            aU.x += __shfl_xor_sync(0xffffffffu, aU.x, 8);
            aU.y += __shfl_xor_sync(0xffffffffu, aU.y, 8);
            aU.z += __shfl_xor_sync(0xffffffffu, aU.z, 8);
            aU.w += __shfl_xor_sync(0xffffffffu, aU.w, 8);
            aU.x += __shfl_xor_sync(0xffffffffu, aU.x, 16);
            aU.y += __shfl_xor_sync(0xffffffffu, aU.y, 16);
            aU.z += __shfl_xor_sync(0xffffffffu, aU.z, 16);
            aU.w += __shfl_xor_sync(0xffffffffu, aU.w, 16);
            if (lane < 8)
                ((float4*)s_pU)[wid*8 + q8] = aU;
        }
        __syncthreads();   // s1

        // ---- C2: reduce -> hid/ihid; inst partials; DSMEM hid broadcast ----
        if (tid < 64) {
            float sI = s_ihe[tid] + s_bI[tid];
            float sH = s_bH[tid];
            #pragma unroll
            for (int s = 0; s < 16; s++) { sI += s_pS[s*64 + tid]; sH += s_pH[s*64 + tid]; }
            float hn = sI + sH; hn = hn > 0.f ? hn : 0.f;
            s_hidloc[tid] = hn;
            out[OUT_OUTPUTS + (t*BSZ + b)*HDIM + ri*64 + tid] = hn;
            if (t == T_STEPS-1) out[OUT_HID + b*HDIM + ri*64 + tid] = hn;
            uint32_t off = a_hid + (uint32_t)(wb*256 + ri*64 + tid)*4u;
            #pragma unroll
            for (uint32_t pr = 0; pr < CSIZE; pr++) st_cluster_f32(off, pr, hn);
            // inst partial logits over owned ihid dims
            float p0 = sI*whi0, p1 = sI*whi1, p2 = sI*whi2;
            #pragma unroll
            for (int off2 = 16; off2; off2 >>= 1) {
                p0 += __shfl_down_sync(0xffffffffu, p0, off2);
                p1 += __shfl_down_sync(0xffffffffu, p1, off2);
                p2 += __shfl_down_sync(0xffffffffu, p2, off2);
            }
            if (lane == 0) {
                s_instw[wid*3 + 0] = p0;
                s_instw[wid*3 + 1] = p1;
                s_instw[wid*3 + 2] = p2;
            }
        }
        __syncthreads();   // s3

        // ---- D: inst DSMEM (3 threads) + push partials (all) ----
        if (tid < 3) {
            float a = s_instw[tid] + s_instw[3 + tid];
            uint32_t addr = a_instp + (uint32_t)(ri*4 + tid)*4u;
            #pragma unroll
            for (uint32_t pr = 0; pr < CSIZE; pr++) st_cluster_f32(addr, pr, a);
        }
        {
            const int q = tid & 31, kb = (tid >> 5)*4;
            float4 aP = make_float4(0.f,0.f,0.f,0.f);
            #pragma unroll
            for (int kk = 0; kk < 4; kk++) {
                int kl = kb + kk;
                float xh = s_hidloc[kl];
                float4 wp = wp4[kl*32 + q];
                aP.x = fmaf(xh,wp.x,aP.x); aP.y = fmaf(xh,wp.y,aP.y);
                aP.z = fmaf(xh,wp.z,aP.z); aP.w = fmaf(xh,wp.w,aP.w);
            }
            ((float4*)s_pP)[(tid>>5)*32 + q] = aP;
        }
        __syncthreads();   // s4

        // ---- E: push reduce -> DSMEM to owning peer; uval (local) ----
        if (tid < 128) {
            float pv = 0.f;
            #pragma unroll
            for (int s = 0; s < 16; s++) pv += s_pP[s*128 + tid];
            st_cluster_f32(a_ppart + (uint32_t)(ri*32 + (tid & 31))*4u, (uint32_t)(tid >> 5), pv);
        } else if (tid < 160) {
            int c = tid - 128;
            float u = s_bu[c];
            #pragma unroll
            for (int s = 0; s < 16; s++) u += s_pU[s*32 + c];
            s_uval[c] = u > 0.f ? u : 0.f;
        }
        __syncthreads();   // s5a: orders DSMEM stores + pU reads before arrive
        if (tid < CSIZE) mbar_arrive_cluster(a_mid, (uint32_t)tid);

        // ---- G-local (peer-independent, overlaps mid wait): Pe conv (L2),
        //      coef + stack preloads ----
        float cc = 0.f, cm = 0.f;
        float so[10];
        const int j  = tid & 31;
        const int i0 = (tid >> 5)*8;
        {
            const int o = tid & 63, ks = tid >> 6;
            const int kmax = (t + 1 < 63) ? (t + 1) : 63;
            float acc = 0.f;
            const int kend = (ks*8 + 8 <= kmax + 1) ? ks*8 + 8 : kmax + 1;
            const float* ep = g_Epr + (size_t)b*64*256 + ri*64 + o;
            for (int k = ks*8; k < kend; k++)
                acc = fmaf(s_coef[t + 1 - k], ep[(size_t)k*256], acc);
            s_pe[ks*64 + o] = acc;

            if (tid < 128) { cc = s_coef[tid]; cm = tid ? s_coef[tid-1] : 0.f; }
            so[0] = (i0 > 0) ? s_stk[(i0-1)*32 + j] : 0.f;
            #pragma unroll
            for (int ii = 0; ii < 9; ii++)
                so[1+ii] = (i0 + ii < 128) ? s_stk[(i0+ii)*32 + j] : 0.f;
        }

        // ---- G2: only warps 0 and 8 block on the mid exchange ----
        if (wid == 0) {
            mbar_wait_cluster(a_mid, (uint32_t)(t & 1));
            float i0v = s_instp[0] + s_instp[4] + s_instp[8]  + s_instp[12] + s_bias[0];
            float i1v = s_instp[1] + s_instp[5] + s_instp[9]  + s_instp[13] + s_bias[1];
            float i2v = s_instp[2] + s_instp[6] + s_instp[10] + s_instp[14] + s_bias[2];
            float m  = fmaxf(i0v, i1v);
            float e0 = expf(i0v - m), e1 = expf(i1v - m);
            float inv = 1.f / (e0 + e1);
            float act0 = e0*inv, act1 = e1*inv;
            float sp = fmaxf(i2v, 0.f) + log1pf(expf(-fabsf(i2v)));
            float g  = 1.f + sp;
            float a0 = powf(act0, g), a1 = powf(act1, g);
            float s  = a0 + a1 + 1e-16f;
            float pp = a0 / s, pq = a1 / s;
            if (lane == 0) {
                s_scal[0] = pp; s_scal[1] = pq;
                if (r == 0) {
                    out[OUT_ACTS + (t*BSZ + b)*2 + 0] = pp;
                    out[OUT_ACTS + (t*BSZ + b)*2 + 1] = pq;
                }
            }
        } else if (wid == 8) {
            mbar_wait_cluster(a_mid, (uint32_t)(t & 1));
            int c = lane;
            float pv = s_ppart[c] + s_ppart[32+c] + s_ppart[64+c] + s_ppart[96+c] + s_bp[c];
            s_push[c] = pv > 0.f ? pv : 0.f;
        }
        __syncthreads();   // s5

        // ---- I1: ihe/coef update; stack rows 0-1; tops DSMEM ----
        const float pp = s_scal[0], pq = s_scal[1];
        if (tid < 64) {
            float Pe = 0.f;
            #pragma unroll
            for (int s = 0; s < 8; s++) Pe += s_pe[s*64 + tid];
            s_ihe[tid] = fmaf(pp, Pe, pq*s_ihe[tid]);
        }
        if (tid < 128) s_coef[tid] = fmaf(pp, cc, pq*cm);
        {
            #pragma unroll
            for (int ii = 0; ii < 2; ii++) {
                int i = i0 + ii;
                float nv;
                if (i == 0) nv = fmaf(pp, s_push[j], pq*s_uval[j]);
                else        nv = fmaf(pp, so[ii],    pq*so[ii+2]);
                s_stk[i*32 + j] = nv;
                if (i == 0) out[OUT_TOP + (t*BSZ + b)*SDIM + ri*32 + j] = nv;
                if (i <= 1) {
                    uint32_t off = a_tops + (uint32_t)(wb*256 + i*128 + ri*32 + j)*4u;
                    #pragma unroll
                    for (uint32_t pr = 0; pr < CSIZE; pr++) st_cluster_f32(off, pr, nv);
                }
            }
        }
        __syncthreads();   // s6: orders tops/hid DSMEM stores before end arrive
        if (tid < CSIZE) mbar_arrive_cluster(a_end, (uint32_t)tid);

        // ---- I2: stack rows 2..7 (local; ordered by next step's s1) ----
        {
            #pragma unroll
            for (int ii = 2; ii < 8; ii++) {
                int i = i0 + ii;
                float nv;
                if (i == 127) nv = fmaf(pp, so[ii], pq*s_emp[j]);
                else          nv = fmaf(pp, so[ii], pq*so[ii+2]);
                s_stk[i*32 + j] = nv;
            }
        }
    }

    // ensure all peers' final DSMEM stores into us have arrived before exit
    mbar_wait_cluster(a_end, (uint32_t)(T_STEPS & 1));

    // ---- final stack output ----
    for (int idx = tid; idx < 128*32; idx += NTHR) {
        int i = idx >> 5, jc = idx & 31;
        out[OUT_STACK + b*SSZ*SDIM + i*SDIM + ri*32 + jc] = s_stk[idx];
    }
}

extern "C" void kernel_launch(void* const* d_in, const int* in_sizes, int n_in,
                              void* d_out, int out_size)
{
    const int*   inputs = (const int*)  d_in[0];
    const float* emb_W  = (const float*)d_in[1];
    const float* W_e2h  = (const float*)d_in[2];
    const float* b_e2h  = (const float*)d_in[3];
    const float* W_s2h  = (const float*)d_in[4];
    const float* b_s2h  = (const float*)d_in[5];
    const float* W_h2h  = (const float*)d_in[6];
    const float* b_h2h  = (const float*)d_in[7];
    const float* W_h2i  = (const float*)d_in[8];
    const float* b_h2i  = (const float*)d_in[9];
    const float* W_h2s  = (const float*)d_in[10];
    const float* b_h2s  = (const float*)d_in[11];
    const float* W_s2u  = (const float*)d_in[12];
    const float* b_s2u  = (const float*)d_in[13];
    const float* empty  = (const float*)d_in[14];
    float* out = (float*)d_out;

    prep_kernel<<<1024, 256>>>(W_e2h, W_s2h, W_h2h, W_h2s, W_s2u);
    prep2_kernel<<<256, 256>>>(inputs, emb_W);

    static int configured = 0;
    if (!configured) {
        cudaFuncSetAttribute(srnn_kernel, cudaFuncAttributeMaxDynamicSharedMemorySize, SMEM_BYTES);
        configured = 1;
    }
    srnn_kernel<<<BSZ*CSIZE, NTHR, SMEM_BYTES>>>(b_e2h, b_s2h, b_h2h,
                                                 W_h2i, b_h2i, b_h2s, b_s2u,
                                                 empty, out);
}